// round 7
// baseline (speedup 1.0000x reference)
#include <cuda_runtime.h>
#include <cuda_fp16.h>
#include <cstdint>

#define IN_F   2048
#define OUT_F  2048
#define BATCH  8192
#define KTOPF  1844.0f

#define BK      64          // halfs per K-chunk (128 bytes per row)
#define NCH     (IN_F / BK) // 32 chunks per tile
#define NSTAGE  3
#define STAGE_BYTES 32768u  // A 16KB + B 16KB
#define MBAR_BASE   (NSTAGE * STAGE_BYTES)          // 96 KB
#define SMEM_BYTES  (MBAR_BASE + 64u)               // + mbarrier block

#define NSLOT   296         // persistent CTAs = 148 SMs x 2
#define NTILES  1024        // (8192/128) x (2048/128)

// Scratch (static __device__ allocations are allowed)
__device__ float  g_aw[OUT_F];
__device__ __half g_Wh[OUT_F * IN_F];   // 8 MB  W[r][c] fp16, k-contiguous
__device__ __half g_Xh[BATCH * IN_F];   // 32 MB x fp16, k-contiguous

// ---------------------------------------------------------------- helpers
static __device__ __forceinline__ uint32_t smem_u32(const void* p) {
    uint32_t a;
    asm("{ .reg .u64 t; cvta.to.shared.u64 t, %1; cvt.u32.u64 %0, t; }" : "=r"(a) : "l"(p));
    return a;
}

static __device__ __forceinline__ void cpa16(uint32_t s, const void* g) {
    asm volatile("cp.async.cg.shared.global [%0], [%1], 16;" :: "r"(s), "l"(g) : "memory");
}

static __device__ __forceinline__ void cpa_mbar_arrive(uint32_t mbar) {
    asm volatile("cp.async.mbarrier.arrive.noinc.shared::cta.b64 [%0];" :: "r"(mbar) : "memory");
}

static __device__ __forceinline__ void mbar_init(uint32_t a, uint32_t n) {
    asm volatile("mbarrier.init.shared.b64 [%0], %1;" :: "r"(a), "r"(n) : "memory");
}

static __device__ __forceinline__ void mbar_arrive(uint32_t a) {
    asm volatile("mbarrier.arrive.shared::cta.b64 _, [%0];" :: "r"(a) : "memory");
}

static __device__ __forceinline__ void mbar_wait(uint32_t mbar, uint32_t parity) {
    asm volatile(
        "{\n\t"
        ".reg .pred P1;\n\t"
        "WAIT_LOOP_%=:\n\t"
        "mbarrier.try_wait.parity.acquire.cta.shared::cta.b64 P1, [%0], %1, 0x989680;\n\t"
        "@P1 bra.uni WAIT_DONE_%=;\n\t"
        "bra.uni WAIT_LOOP_%=;\n\t"
        "WAIT_DONE_%=:\n\t"
        "}"
        :: "r"(mbar), "r"(parity) : "memory");
}

static __device__ __forceinline__ void ldm_x4(uint32_t* r, uint32_t addr) {
    asm volatile("ldmatrix.sync.aligned.m8n8.x4.shared.b16 {%0,%1,%2,%3}, [%4];"
                 : "=r"(r[0]), "=r"(r[1]), "=r"(r[2]), "=r"(r[3]) : "r"(addr));
}

// ---------------------------------------------------------------- kernel 1: gate
__global__ void alpha_kernel(const float* __restrict__ alpha) {
    __shared__ float sh[8];
    const int tid = threadIdx.x;
    float v[8];
    float m = -3.0e38f;
#pragma unroll
    for (int i = 0; i < 8; i++) { v[i] = alpha[tid + (i << 8)]; m = fmaxf(m, v[i]); }
#pragma unroll
    for (int o = 16; o; o >>= 1) m = fmaxf(m, __shfl_xor_sync(0xffffffffu, m, o));
    if ((tid & 31) == 0) sh[tid >> 5] = m;
    __syncthreads();
    float M = sh[0];
#pragma unroll
    for (int i = 1; i < 8; i++) M = fmaxf(M, sh[i]);
    __syncthreads();
    float s = 0.f;
#pragma unroll
    for (int i = 0; i < 8; i++) { v[i] = expf(v[i] - M); s += v[i]; }
#pragma unroll
    for (int o = 16; o; o >>= 1) s += __shfl_xor_sync(0xffffffffu, s, o);
    if ((tid & 31) == 0) sh[tid >> 5] = s;
    __syncthreads();
    float S = 0.f;
#pragma unroll
    for (int i = 0; i < 8; i++) S += sh[i];
    const float scale = KTOPF / S;
#pragma unroll
    for (int i = 0; i < 8; i++) g_aw[tid + (i << 8)] = fminf(v[i] * scale, 1.0f);
}

// ---------------------------------------------------------------- kernel 2: prep (merged)
// blocks [0, 8192):      quantize x -> g_Xh (fp16)
// blocks [8192, 9216):   build dense W -> g_Wh : W[r][c] = fp16(V[(r-c)&2047][c]*aw)
__global__ void __launch_bounds__(256) prep_kernel(const float* __restrict__ x,
                                                   const float* __restrict__ V) {
    const int tid = threadIdx.x;
    if (blockIdx.x < 8192) {
        const int idx = blockIdx.x * 256 + tid;
        const float4* src = (const float4*)x + ((size_t)idx << 1);
        const float4 v0 = src[0], v1 = src[1];
        __half2 h[4];
        h[0] = __floats2half2_rn(v0.x, v0.y);
        h[1] = __floats2half2_rn(v0.z, v0.w);
        h[2] = __floats2half2_rn(v1.x, v1.y);
        h[3] = __floats2half2_rn(v1.z, v1.w);
        *(uint4*)(g_Xh + ((size_t)idx << 3)) = *(uint4*)h;
        return;
    }
    __shared__ float s[127][65];
    const int b = blockIdx.x - 8192;
    const int r0 = (b >> 5) << 6;
    const int c0 = (b & 31) << 6;
    const int q0 = r0 - c0 - 63;   // p = q0 + (r_local - c_local + 63)

#pragma unroll
    for (int i = tid; i < 127 * 64; i += 256) {
        const int vr = i >> 6;          // 0..126
        const int vc = i & 63;
        const int p = (q0 + vr) & 2047;
        s[vr][vc] = V[((size_t)p << 11) + c0 + vc] * g_aw[p];
    }
    __syncthreads();

#pragma unroll
    for (int pass = 0; pass < 4; pass++) {
        const int rl = (pass << 4) + (tid >> 4);     // 0..63
        const int cl = (tid & 15) << 2;              // 0..60
        __half h[4];
#pragma unroll
        for (int i = 0; i < 4; i++)
            h[i] = __float2half_rn(s[rl - (cl + i) + 63][cl + i]);
        *(uint2*)(g_Wh + ((size_t)(r0 + rl) << 11) + c0 + cl) = *(uint2*)h;
    }
}

// ---------------------------------------------------------------- stage loader (128 threads)
static __device__ __forceinline__ void load_stage(uint32_t sb, int tid,
                                                  const __half* gA, const __half* gB,
                                                  int stage) {
    const uint32_t sA = sb + (uint32_t)stage * STAGE_BYTES;
    const uint32_t sB = sA + 16384u;
#pragma unroll
    for (int i = 0; i < 8; i++) {
        const int cid = tid + (i << 7);
        const int row = cid >> 3;
        const int ch  = cid & 7;
        const uint32_t so = ((uint32_t)row << 7) + ((uint32_t)(ch ^ (row & 7)) << 4);
        cpa16(sA + so, gA + (size_t)row * IN_F + ch * 8);
        cpa16(sB + so, gB + (size_t)row * IN_F + ch * 8);
    }
}

// flat chunk index -> global A/B pointers for this CTA's tile sequence
static __device__ __forceinline__ void chunk_ptrs(int bid, int fc,
                                                  const __half*& gA, const __half*& gB) {
    const int tileid = bid + ((fc >> 5) * NSLOT);
    const int k0 = (fc & 31) * BK;
    gA = g_Xh + ((size_t)(tileid >> 4) << 7) * IN_F + k0;   // tm*128 rows
    gB = g_Wh + ((size_t)(tileid & 15) << 7) * IN_F + k0;   // tn*128 rows
}

// ---------------------------------------------------------------- kernel 3: persistent GEMM
// out[m][n] = sum_k Xh[m][k] * Wh[n][k], fp16 mma.sync m16n8k16, fp32 accum.
// 296 persistent CTAs, 128x128 tiles assigned bid, bid+296, ...; the mbarrier
// cp.async pipeline runs over a flat chunk stream ACROSS tile boundaries, so
// the pipe never drains between tiles and epilogues overlap in-flight loads.
__global__ void __launch_bounds__(128, 2) gemm_kernel(float* __restrict__ OUT) {
    extern __shared__ __align__(1024) char smem[];
    const uint32_t sb = smem_u32(smem);
    const int tid = threadIdx.x;
    const int lane = tid & 31;
    const int wid = tid >> 5;
    const int warp_m = wid >> 1;   // 0..1
    const int warp_n = wid & 1;    // 0..1
    const int bid = blockIdx.x;

    const int ntiles = (NTILES - bid + NSLOT - 1) / NSLOT;  // 4 or 3
    const int total = ntiles << 5;

    // mbarrier addresses: full[s] at MBAR_BASE + 16s, empty[s] at +16s+8
    const uint32_t mb = sb + MBAR_BASE;
    if (tid == 0) {
#pragma unroll
        for (int s = 0; s < NSTAGE; s++) {
            mbar_init(mb + 16u * s, 128u);     // full: one cp.async-arrive per thread
            mbar_init(mb + 16u * s + 8u, 4u);  // empty: one arrive per warp
        }
    }
    __syncthreads();   // publish mbarrier init

    float c[4][8][4];
#pragma unroll
    for (int mt = 0; mt < 4; mt++)
#pragma unroll
        for (int nt = 0; nt < 8; nt++)
#pragma unroll
            for (int q = 0; q < 4; q++) c[mt][nt][q] = 0.f;

    // prologue: fill stages 0 and 1 with flat chunks 0, 1
    {
        const __half *gA, *gB;
        chunk_ptrs(bid, 0, gA, gB);
        load_stage(sb, tid, gA, gB, 0);
        cpa_mbar_arrive(mb + 0u);
        chunk_ptrs(bid, 1, gA, gB);
        load_stage(sb, tid, gA, gB, 1);
        cpa_mbar_arrive(mb + 16u);
    }

    const uint32_t lane15 = lane & 15;
    const uint32_t lane7  = lane & 7;
    const uint32_t laneHi = lane >> 4;        // 0/1
    const uint32_t laneB  = (lane >> 3) & 1;  // 0/1

    int cs = 0, cph = 0;          // consumer stage / phase
    int ps = 2, pph = 1;          // producer stage / phase (first empty-wait passes)
    for (int fc = 0; fc < total; fc++) {
        mbar_wait(mb + 16u * (uint32_t)cs, (uint32_t)cph);

        const uint32_t bufA = sb + (uint32_t)cs * STAGE_BYTES;
        const uint32_t bufB = bufA + 16384u;

#pragma unroll
        for (int kk = 0; kk < 4; kk++) {
            uint32_t a[4][4];
            uint32_t b[8][2];
            const uint32_t swA = (((uint32_t)(kk * 2) + laneHi) ^ lane7) << 4;
#pragma unroll
            for (int mt = 0; mt < 4; mt++) {
                const uint32_t row = (uint32_t)(warp_m * 64 + mt * 16) + lane15;
                ldm_x4(a[mt], bufA + (row << 7) + swA);
            }
            const uint32_t swB = (((uint32_t)(kk * 2) + laneB) ^ lane7) << 4;
#pragma unroll
            for (int np = 0; np < 4; np++) {
                const uint32_t row = (uint32_t)(warp_n * 64) + ((uint32_t)(2 * np) + laneHi) * 8 + lane7;
                uint32_t r4[4];
                ldm_x4(r4, bufB + (row << 7) + swB);
                b[2 * np    ][0] = r4[0]; b[2 * np    ][1] = r4[1];
                b[2 * np + 1][0] = r4[2]; b[2 * np + 1][1] = r4[3];
            }
#pragma unroll
            for (int mt = 0; mt < 4; mt++)
#pragma unroll
                for (int nt = 0; nt < 8; nt++) {
                    asm volatile(
                        "mma.sync.aligned.m16n8k16.row.col.f32.f16.f16.f32 "
                        "{%0,%1,%2,%3}, {%4,%5,%6,%7}, {%8,%9}, {%0,%1,%2,%3};"
                        : "+f"(c[mt][nt][0]), "+f"(c[mt][nt][1]),
                          "+f"(c[mt][nt][2]), "+f"(c[mt][nt][3])
                        : "r"(a[mt][0]), "r"(a[mt][1]), "r"(a[mt][2]), "r"(a[mt][3]),
                          "r"(b[nt][0]), "r"(b[nt][1]));
                }
        }

        // this warp is done reading stage cs (ldmatrix is warp-synchronous)
        if (lane == 0) mbar_arrive(mb + 16u * (uint32_t)cs + 8u);

        // refill: flat chunk fc+2 into stage ps (may belong to the NEXT tile)
        if (fc + 2 < total) {
            mbar_wait(mb + 16u * (uint32_t)ps + 8u, (uint32_t)pph);
            const __half *gA, *gB;
            chunk_ptrs(bid, fc + 2, gA, gB);
            load_stage(sb, tid, gA, gB, ps);
            cpa_mbar_arrive(mb + 16u * (uint32_t)ps);
            if (++ps == NSTAGE) { ps = 0; pph ^= 1; }
        }
        if (++cs == NSTAGE) { cs = 0; cph ^= 1; }

        // tile finished -> epilogue (regs only, no sync), reset accumulators
        if ((fc & 31) == 31) {
            const int tileid = bid + ((fc >> 5) * NSLOT);
            const int m0 = (tileid >> 4) << 7;
            const int n0 = (tileid & 15) << 7;
#pragma unroll
            for (int mt = 0; mt < 4; mt++) {
                const int r = m0 + warp_m * 64 + mt * 16 + (lane >> 2);
#pragma unroll
                for (int nt = 0; nt < 8; nt++) {
                    const int col = n0 + warp_n * 64 + nt * 8 + (lane & 3) * 2;
                    float2 v0, v1;
                    v0.x = c[mt][nt][0]; v0.y = c[mt][nt][1];
                    v1.x = c[mt][nt][2]; v1.y = c[mt][nt][3];
                    *(float2*)(OUT + (size_t)r * OUT_F + col) = v0;
                    *(float2*)(OUT + (size_t)(r + 8) * OUT_F + col) = v1;
                    c[mt][nt][0] = 0.f; c[mt][nt][1] = 0.f;
                    c[mt][nt][2] = 0.f; c[mt][nt][3] = 0.f;
                }
            }
        }
    }
}

// ---------------------------------------------------------------- launch
extern "C" void kernel_launch(void* const* d_in, const int* in_sizes, int n_in,
                              void* d_out, int out_size) {
    const float* x     = (const float*)d_in[0];
    const float* V     = (const float*)d_in[1];
    const float* alpha = (const float*)d_in[2];
    float* out = (float*)d_out;

    static int configured = 0;
    if (!configured) {
        cudaFuncSetAttribute(gemm_kernel, cudaFuncAttributeMaxDynamicSharedMemorySize, SMEM_BYTES);
        configured = 1;
    }

    alpha_kernel<<<1, 256>>>(alpha);
    prep_kernel<<<8192 + 1024, 256>>>(x, V);
    gemm_kernel<<<NSLOT, 128, SMEM_BYTES>>>(out);
}

// round 9
// speedup vs baseline: 1.1401x; 1.1401x over previous
#include <cuda_runtime.h>
#include <cuda_fp16.h>
#include <cstdint>

#define IN_F   2048
#define OUT_F  2048
#define BATCH  8192
#define KTOPF  1844.0f

#define BK      64          // halfs per K-chunk (128 bytes per row)
#define NCH     (IN_F / BK) // 32 chunks
#define NSTAGE  3
#define STAGE_BYTES 32768u  // A 16KB + B 16KB
#define MBAR_BASE   (NSTAGE * STAGE_BYTES)          // 96 KB
#define SMEM_BYTES  (MBAR_BASE + 64u)               // + mbarrier block

// Scratch (static __device__ allocations are allowed)
__device__ __half g_Wh[OUT_F * IN_F];   // 8 MB  W[r][c] fp16, k-contiguous
__device__ __half g_Xh[BATCH * IN_F];   // 32 MB x fp16, k-contiguous

// ---------------------------------------------------------------- helpers
static __device__ __forceinline__ uint32_t smem_u32(const void* p) {
    uint32_t a;
    asm("{ .reg .u64 t; cvta.to.shared.u64 t, %1; cvt.u32.u64 %0, t; }" : "=r"(a) : "l"(p));
    return a;
}

static __device__ __forceinline__ void cpa16(uint32_t s, const void* g) {
    asm volatile("cp.async.cg.shared.global [%0], [%1], 16;" :: "r"(s), "l"(g) : "memory");
}

static __device__ __forceinline__ void cpa_mbar_arrive(uint32_t mbar) {
    asm volatile("cp.async.mbarrier.arrive.noinc.shared::cta.b64 [%0];" :: "r"(mbar) : "memory");
}

static __device__ __forceinline__ void mbar_init(uint32_t a, uint32_t n) {
    asm volatile("mbarrier.init.shared.b64 [%0], %1;" :: "r"(a), "r"(n) : "memory");
}

static __device__ __forceinline__ void mbar_arrive(uint32_t a) {
    asm volatile("mbarrier.arrive.shared::cta.b64 _, [%0];" :: "r"(a) : "memory");
}

static __device__ __forceinline__ void mbar_wait(uint32_t mbar, uint32_t parity) {
    asm volatile(
        "{\n\t"
        ".reg .pred P1;\n\t"
        "WAIT_LOOP_%=:\n\t"
        "mbarrier.try_wait.parity.acquire.cta.shared::cta.b64 P1, [%0], %1, 0x989680;\n\t"
        "@P1 bra.uni WAIT_DONE_%=;\n\t"
        "bra.uni WAIT_LOOP_%=;\n\t"
        "WAIT_DONE_%=:\n\t"
        "}"
        :: "r"(mbar), "r"(parity) : "memory");
}

static __device__ __forceinline__ void ldm_x4(uint32_t* r, uint32_t addr) {
    asm volatile("ldmatrix.sync.aligned.m8n8.x4.shared.b16 {%0,%1,%2,%3}, [%4];"
                 : "=r"(r[0]), "=r"(r[1]), "=r"(r[2]), "=r"(r[3]) : "r"(addr));
}

// ---------------------------------------------------------------- kernel 1: prep (single launch)
// blocks [0, 8192):     quantize x -> g_Xh (fp16)
// blocks [8192, 9216):  inline softmax gate + build dense W -> g_Wh
//                       W[r][c] = fp16( V[(r-c)&2047][c] * aw[(r-c)&2047] )
__global__ void __launch_bounds__(256) prep_kernel(const float* __restrict__ x,
                                                   const float* __restrict__ V,
                                                   const float* __restrict__ alpha) {
    const int tid = threadIdx.x;
    if (blockIdx.x < 8192) {
        const int idx = blockIdx.x * 256 + tid;
        const float4* src = (const float4*)x + ((size_t)idx << 1);
        const float4 v0 = src[0], v1 = src[1];
        __half2 h[4];
        h[0] = __floats2half2_rn(v0.x, v0.y);
        h[1] = __floats2half2_rn(v0.z, v0.w);
        h[2] = __floats2half2_rn(v1.x, v1.y);
        h[3] = __floats2half2_rn(v1.z, v1.w);
        *(uint4*)(g_Xh + ((size_t)idx << 3)) = *(uint4*)h;
        return;
    }

    __shared__ float aw_s[2048];
    __shared__ float red[8];
    __shared__ float s[127][65];

    // ---- inline softmax gate: aw = min(K * softmax(alpha), 1)
    {
        float v[8];
        float m = -3.0e38f;
#pragma unroll
        for (int i = 0; i < 8; i++) { v[i] = alpha[tid + (i << 8)]; m = fmaxf(m, v[i]); }
#pragma unroll
        for (int o = 16; o; o >>= 1) m = fmaxf(m, __shfl_xor_sync(0xffffffffu, m, o));
        if ((tid & 31) == 0) red[tid >> 5] = m;
        __syncthreads();
        float M = red[0];
#pragma unroll
        for (int i = 1; i < 8; i++) M = fmaxf(M, red[i]);
        __syncthreads();
        float sum = 0.f;
#pragma unroll
        for (int i = 0; i < 8; i++) { v[i] = expf(v[i] - M); sum += v[i]; }
#pragma unroll
        for (int o = 16; o; o >>= 1) sum += __shfl_xor_sync(0xffffffffu, sum, o);
        if ((tid & 31) == 0) red[tid >> 5] = sum;
        __syncthreads();
        float S = 0.f;
#pragma unroll
        for (int i = 0; i < 8; i++) S += red[i];
        const float scale = KTOPF / S;
#pragma unroll
        for (int i = 0; i < 8; i++) aw_s[tid + (i << 8)] = fminf(v[i] * scale, 1.0f);
    }
    __syncthreads();

    // ---- build 64x64 W tile from the 127-row V window
    const int b = blockIdx.x - 8192;
    const int r0 = (b >> 5) << 6;
    const int c0 = (b & 31) << 6;
    const int q0 = r0 - c0 - 63;   // p = q0 + (r_local - c_local + 63)

#pragma unroll
    for (int i = tid; i < 127 * 64; i += 256) {
        const int vr = i >> 6;          // 0..126
        const int vc = i & 63;
        const int p = (q0 + vr) & 2047;
        s[vr][vc] = V[((size_t)p << 11) + c0 + vc] * aw_s[p];
    }
    __syncthreads();

#pragma unroll
    for (int pass = 0; pass < 4; pass++) {
        const int rl = (pass << 4) + (tid >> 4);     // 0..63
        const int cl = (tid & 15) << 2;              // 0..60
        __half h[4];
#pragma unroll
        for (int i = 0; i < 4; i++)
            h[i] = __float2half_rn(s[rl - (cl + i) + 63][cl + i]);
        *(uint2*)(g_Wh + ((size_t)(r0 + rl) << 11) + c0 + cl) = *(uint2*)h;
    }
}

// ---------------------------------------------------------------- stage loader (128 threads)
static __device__ __forceinline__ void load_stage(uint32_t sb, int tid,
                                                  const __half* gA0, const __half* gB0,
                                                  int stage, int kblk) {
    const uint32_t sA = sb + (uint32_t)stage * STAGE_BYTES;
    const uint32_t sB = sA + 16384u;
    const __half* gA = gA0 + kblk * BK;
    const __half* gB = gB0 + kblk * BK;
#pragma unroll
    for (int i = 0; i < 8; i++) {
        const int cid = tid + (i << 7);
        const int row = cid >> 3;
        const int ch  = cid & 7;
        const uint32_t so = ((uint32_t)row << 7) + ((uint32_t)(ch ^ (row & 7)) << 4);
        cpa16(sA + so, gA + (size_t)row * IN_F + ch * 8);
        cpa16(sB + so, gB + (size_t)row * IN_F + ch * 8);
    }
}

// ---------------------------------------------------------------- kernel 2: GEMM (R6, unchanged)
// out[m][n] = sum_k Xh[m][k] * Wh[n][k], fp16 mma.sync m16n8k16, fp32 accum.
// CTA tile 128x128x64, 4 warps (2 M x 2 N), warp tile 64x64, 2 CTAs/SM.
// Mainloop has NO __syncthreads: per-stage mbarrier pipeline.
__global__ void __launch_bounds__(128, 2) gemm_kernel(float* __restrict__ OUT) {
    extern __shared__ __align__(1024) char smem[];
    const uint32_t sb = smem_u32(smem);
    const int tid = threadIdx.x;
    const int lane = tid & 31;
    const int wid = tid >> 5;
    const int warp_m = wid >> 1;   // 0..1
    const int warp_n = wid & 1;    // 0..1
    const int m0 = blockIdx.y * 128;
    const int n0 = blockIdx.x * 128;

    const __half* gA0 = g_Xh + (size_t)m0 * IN_F;
    const __half* gB0 = g_Wh + (size_t)n0 * IN_F;

    // mbarrier addresses: full[s] at MBAR_BASE + 16s, empty[s] at +16s+8
    const uint32_t mb = sb + MBAR_BASE;
    if (tid == 0) {
#pragma unroll
        for (int s = 0; s < NSTAGE; s++) {
            mbar_init(mb + 16u * s, 128u);     // full: one cp.async-arrive per thread
            mbar_init(mb + 16u * s + 8u, 4u);  // empty: one arrive per warp
        }
    }
    __syncthreads();   // only sync in the kernel: publish mbarrier init

    float c[4][8][4];
#pragma unroll
    for (int mt = 0; mt < 4; mt++)
#pragma unroll
        for (int nt = 0; nt < 8; nt++)
#pragma unroll
            for (int q = 0; q < 4; q++) c[mt][nt][q] = 0.f;

    // prologue: fill stages 0 and 1 (chunks 0, 1)
    load_stage(sb, tid, gA0, gB0, 0, 0);
    cpa_mbar_arrive(mb + 0u);
    load_stage(sb, tid, gA0, gB0, 1, 1);
    cpa_mbar_arrive(mb + 16u);

    const uint32_t lane15 = lane & 15;
    const uint32_t lane7  = lane & 7;
    const uint32_t laneHi = lane >> 4;        // 0/1
    const uint32_t laneB  = (lane >> 3) & 1;  // 0/1

    int cs = 0, cph = 0;          // consumer stage / phase
    int ps = 2, pph = 1;          // producer stage / phase (first empty-wait passes)
    for (int s = 0; s < NCH; s++) {
        mbar_wait(mb + 16u * (uint32_t)cs, (uint32_t)cph);

        const uint32_t bufA = sb + (uint32_t)cs * STAGE_BYTES;
        const uint32_t bufB = bufA + 16384u;

#pragma unroll
        for (int kk = 0; kk < 4; kk++) {
            uint32_t a[4][4];
            uint32_t b[8][2];
            const uint32_t swA = (((uint32_t)(kk * 2) + laneHi) ^ lane7) << 4;
#pragma unroll
            for (int mt = 0; mt < 4; mt++) {
                const uint32_t row = (uint32_t)(warp_m * 64 + mt * 16) + lane15;
                ldm_x4(a[mt], bufA + (row << 7) + swA);
            }
            const uint32_t swB = (((uint32_t)(kk * 2) + laneB) ^ lane7) << 4;
#pragma unroll
            for (int np = 0; np < 4; np++) {
                const uint32_t row = (uint32_t)(warp_n * 64) + ((uint32_t)(2 * np) + laneHi) * 8 + lane7;
                uint32_t r4[4];
                ldm_x4(r4, bufB + (row << 7) + swB);
                b[2 * np    ][0] = r4[0]; b[2 * np    ][1] = r4[1];
                b[2 * np + 1][0] = r4[2]; b[2 * np + 1][1] = r4[3];
            }
#pragma unroll
            for (int mt = 0; mt < 4; mt++)
#pragma unroll
                for (int nt = 0; nt < 8; nt++) {
                    asm volatile(
                        "mma.sync.aligned.m16n8k16.row.col.f32.f16.f16.f32 "
                        "{%0,%1,%2,%3}, {%4,%5,%6,%7}, {%8,%9}, {%0,%1,%2,%3};"
                        : "+f"(c[mt][nt][0]), "+f"(c[mt][nt][1]),
                          "+f"(c[mt][nt][2]), "+f"(c[mt][nt][3])
                        : "r"(a[mt][0]), "r"(a[mt][1]), "r"(a[mt][2]), "r"(a[mt][3]),
                          "r"(b[nt][0]), "r"(b[nt][1]));
                }
        }

        // this warp is done reading stage cs (ldmatrix is warp-synchronous)
        if (lane == 0) mbar_arrive(mb + 16u * (uint32_t)cs + 8u);

        // refill: chunk s+2 into stage ps, once all warps have drained its old chunk
        if (s + 2 < NCH) {
            mbar_wait(mb + 16u * (uint32_t)ps + 8u, (uint32_t)pph);
            load_stage(sb, tid, gA0, gB0, ps, s + 2);
            cpa_mbar_arrive(mb + 16u * (uint32_t)ps);
            if (++ps == NSTAGE) { ps = 0; pph ^= 1; }
        }
        if (++cs == NSTAGE) { cs = 0; cph ^= 1; }
    }

    // epilogue: direct float2 stores (accums are private; no sync needed)
#pragma unroll
    for (int mt = 0; mt < 4; mt++) {
        const int r = m0 + warp_m * 64 + mt * 16 + (lane >> 2);
#pragma unroll
        for (int nt = 0; nt < 8; nt++) {
            const int col = n0 + warp_n * 64 + nt * 8 + (lane & 3) * 2;
            float2 v0, v1;
            v0.x = c[mt][nt][0]; v0.y = c[mt][nt][1];
            v1.x = c[mt][nt][2]; v1.y = c[mt][nt][3];
            *(float2*)(OUT + (size_t)r * OUT_F + col) = v0;
            *(float2*)(OUT + (size_t)(r + 8) * OUT_F + col) = v1;
        }
    }
}

// ---------------------------------------------------------------- launch
extern "C" void kernel_launch(void* const* d_in, const int* in_sizes, int n_in,
                              void* d_out, int out_size) {
    const float* x     = (const float*)d_in[0];
    const float* V     = (const float*)d_in[1];
    const float* alpha = (const float*)d_in[2];
    float* out = (float*)d_out;

    static int configured = 0;
    if (!configured) {
        cudaFuncSetAttribute(gemm_kernel, cudaFuncAttributeMaxDynamicSharedMemorySize, SMEM_BYTES);
        configured = 1;
    }

    prep_kernel<<<8192 + 1024, 256>>>(x, V, alpha);
    gemm_kernel<<<dim3(OUT_F / 128, BATCH / 128), 128, SMEM_BYTES>>>(out);
}